// round 1
// baseline (speedup 1.0000x reference)
#include <cuda_runtime.h>
#include <cuda_bf16.h>

// Batched GCN (512 graphs x 100 nodes, in-degree 16) fully fused: one CTA per
// graph. All intermediates live in SMEM. Layer-2 uses transform-before-
// aggregate (aggregation is linear) to shrink the second gather from 100 to
// 20 dims. Heads: softmax over a length-1 token is identically 1, so
// Z = (x @ Wv^T) @ Wo^T exactly; Wq/Wk are dead.

#define NPG   100
#define DEG   16
#define DIN   100
#define H1    100
#define DG    20
#define P2D   200
#define P3D   100

#define PX    104   // pitch (floats) of 100-wide data buffers (float4 friendly)
#define PW    105   // pitch of transposed W1 (odd -> conflict-free col reads)
#define PT    24    // pitch of 20-wide buffers

// ---- shared memory layout (element offsets, floats unless noted) ----
#define OFF_X     0                         // 112*104 = 11648  (feat, later h1)
#define OFF_A     (OFF_X  + 112*PX)         // 11648            (agg1)
#define OFF_W     (OFF_A  + 112*PX)         // 10516            (W1^T, pitch 105)
#define OFF_W2    (OFF_W  + 100*PW + 16)    // 2432             (W2^T, pitch 24)
#define OFF_T     (OFF_W2 + 2432)           // 112*24 = 2688    (h1 @ W2^T)
#define OFF_T2    (OFF_T  + 112*PT)         // 2688             (agg2)
#define OFF_VP2   (OFF_T2 + 112*PT)         // 256 partials for v2
#define OFF_VP3   (OFF_VP2 + 256)           // 256 partials for v3
#define OFF_SF    (OFF_VP3 + 256)           // 200 self_feat row
#define OFF_X3    (OFF_SF + 200)            // 100 x3d row
#define OFF_PART  (OFF_X3 + 100)            // 8*20 hg partials
#define OFF_VV    (OFF_PART + 160)          // 64: v2[32], v3[32]
#define OFF_HG2   (OFF_VV + 64)             // 20
#define OFF_O10   (OFF_HG2 + 20)            // 12
#define OFF_EDGE  (OFF_O10 + 12)            // 1600 ints
#define SMEM_ELEMS (OFF_EDGE + 1600)
#define SMEM_BYTES (SMEM_ELEMS * 4)

__global__ __launch_bounds__(256, 1)
void net_kernel(const float* __restrict__ feat,
                const int*   __restrict__ edge_src,
                const float* __restrict__ self_feat,
                const float* __restrict__ x3d,
                const float* __restrict__ W1,  const float* __restrict__ b1,
                const float* __restrict__ W2,  const float* __restrict__ b2,
                const float* __restrict__ Wv2, const float* __restrict__ Wo2,
                const float* __restrict__ g2,  const float* __restrict__ be2,
                const float* __restrict__ Wv3, const float* __restrict__ Wo3,
                const float* __restrict__ g3,  const float* __restrict__ be3,
                const float* __restrict__ Wf1, const float* __restrict__ bf1,
                const float* __restrict__ Wf2, const float* __restrict__ bf2,
                float* __restrict__ out)
{
    extern __shared__ float sm[];
    float* sX   = sm + OFF_X;
    float* sA   = sm + OFF_A;
    float* sW   = sm + OFF_W;
    float* sW2  = sm + OFF_W2;
    float* sT   = sm + OFF_T;
    float* sT2  = sm + OFF_T2;
    float* sVp2 = sm + OFF_VP2;
    float* sVp3 = sm + OFF_VP3;
    float* sSf  = sm + OFF_SF;
    float* sX3  = sm + OFF_X3;
    float* sPart= sm + OFF_PART;
    float* sVv  = sm + OFF_VV;
    float* sHg2 = sm + OFF_HG2;
    float* sO10 = sm + OFF_O10;
    int*   sEdge= (int*)(sm + OFF_EDGE);

    const int g    = blockIdx.x;
    const int tid  = threadIdx.x;
    const int warp = tid >> 5;
    const int lane = tid & 31;

    // ---------------- Phase 1: stage inputs ----------------
    // edges -> local indices
    for (int i = tid; i < NPG * DEG; i += 256)
        sEdge[i] = edge_src[g * (NPG * DEG) + i] - g * NPG;

    // feat tile: 10000 contiguous floats, float4
    {
        const float4* fsrc = (const float4*)(feat + (size_t)g * NPG * DIN);
        for (int i4 = tid; i4 < (NPG * DIN) / 4; i4 += 256) {
            float4 v = fsrc[i4];
            int i = i4 * 4;
            int r = i / DIN;
            int c = i - r * DIN;
            *(float4*)&sX[r * PX + c] = v;
        }
    }
    // W1^T (pitch 105)
    for (int idx = tid; idx < H1 * DIN; idx += 256) {
        int o = idx / DIN, k = idx - o * DIN;
        sW[k * PW + o] = W1[idx];
    }
    // W2^T (pitch 24)
    for (int idx = tid; idx < DG * H1; idx += 256) {
        int d = idx / H1, k = idx - d * H1;
        sW2[k * PT + d] = W2[idx];
    }
    // self_feat / x3d rows
    for (int i = tid; i < P2D; i += 256) sSf[i] = self_feat[g * P2D + i];
    for (int i = tid; i < P3D; i += 256) sX3[i] = x3d[g * P3D + i];
    __syncthreads();

    // ---------------- Phase 2: aggregation 1 (mean over 16 nbrs, 100 dims) ----
    for (int n = warp; n < NPG; n += 8) {
        if (lane < 25) {
            float4 acc = make_float4(0.f, 0.f, 0.f, 0.f);
            int base = n * DEG;
            #pragma unroll
            for (int j = 0; j < DEG; ++j) {
                int s = sEdge[base + j];
                float4 v = *(const float4*)&sX[s * PX + (lane << 2)];
                acc.x += v.x; acc.y += v.y; acc.z += v.z; acc.w += v.w;
            }
            const float inv = 1.f / DEG;
            acc.x *= inv; acc.y *= inv; acc.z *= inv; acc.w *= inv;
            *(float4*)&sA[n * PX + (lane << 2)] = acc;
        }
    }
    __syncthreads();

    // ---------------- Phase 3: GEMM1  h1 = relu(agg1 @ W1^T + b1) -> sX -------
    {
        const int ty = tid >> 4, tx = tid & 15;
        float acc[7][7];
        #pragma unroll
        for (int i = 0; i < 7; ++i)
            #pragma unroll
            for (int j = 0; j < 7; ++j) acc[i][j] = 0.f;

        #pragma unroll 2
        for (int k = 0; k < DIN; ++k) {
            float a[7], w[7];
            #pragma unroll
            for (int i = 0; i < 7; ++i) a[i] = sA[(ty + 16 * i) * PX + k];
            #pragma unroll
            for (int j = 0; j < 7; ++j) w[j] = sW[k * PW + tx + 16 * j];
            #pragma unroll
            for (int i = 0; i < 7; ++i)
                #pragma unroll
                for (int j = 0; j < 7; ++j) acc[i][j] = fmaf(a[i], w[j], acc[i][j]);
        }
        float bb[7];
        #pragma unroll
        for (int j = 0; j < 7; ++j) {
            int c = tx + 16 * j;
            bb[j] = (c < H1) ? b1[c] : 0.f;
        }
        #pragma unroll
        for (int i = 0; i < 7; ++i) {
            int r = ty + 16 * i;
            if (r < NPG) {
                #pragma unroll
                for (int j = 0; j < 7; ++j) {
                    int c = tx + 16 * j;
                    if (c < H1) sX[r * PX + c] = fmaxf(acc[i][j] + bb[j], 0.f);
                }
            }
        }
    }
    __syncthreads();

    // ---------------- Phase 4: GEMM2  t = h1 @ W2^T  (no bias yet) -> sT ------
    {
        const int ty = tid >> 4, tx = tid & 15;
        float acc0[7], acc1[7];
        #pragma unroll
        for (int i = 0; i < 7; ++i) { acc0[i] = 0.f; acc1[i] = 0.f; }

        #pragma unroll 2
        for (int k = 0; k < H1; ++k) {
            float w0 = sW2[k * PT + tx];
            float w1 = sW2[k * PT + tx + 16];   // in-bounds (pitch 24 + pad)
            #pragma unroll
            for (int i = 0; i < 7; ++i) {
                float a = sX[(ty + 16 * i) * PX + k];
                acc0[i] = fmaf(a, w0, acc0[i]);
                acc1[i] = fmaf(a, w1, acc1[i]);
            }
        }
        #pragma unroll
        for (int i = 0; i < 7; ++i) {
            int r = ty + 16 * i;
            if (r < NPG) {
                sT[r * PT + tx] = acc0[i];
                if (tx + 16 < DG) sT[r * PT + tx + 16] = acc1[i];
            }
        }
    }
    __syncthreads();

    // ---------------- Phase 5: aggregation 2 (20 dims) -> sT2 -----------------
    for (int n = warp; n < NPG; n += 8) {
        if (lane < DG) {
            float acc = 0.f;
            int base = n * DEG;
            #pragma unroll
            for (int j = 0; j < DEG; ++j)
                acc += sT[sEdge[base + j] * PT + lane];
            sT2[n * PT + lane] = acc * (1.f / DEG);
        }
    }
    __syncthreads();

    // ---------------- Phase 6: hg partials + attention V partials -------------
    if (lane < DG) {
        float b = b2[lane];
        float acc = 0.f;
        for (int n = warp; n < NPG; n += 8)
            acc += fmaxf(sT2[n * PT + lane] + b, 0.f);
        sPart[warp * DG + lane] = acc;
    }
    {
        // v2[j] = Wv2[j,:] . self_feat[g]   (200)  -> 8 partial chunks of 25
        int j  = tid & 31;
        int pg = tid >> 5;
        {
            const float* wr = Wv2 + j * P2D + pg * 25;
            const float* sp = sSf + pg * 25;
            float acc = 0.f;
            #pragma unroll
            for (int p = 0; p < 25; ++p) acc = fmaf(wr[p], sp[p], acc);
            sVp2[pg * 32 + j] = acc;
        }
        // v3[j] = Wv3[j,:] . x3d[g]  (100) -> 8 chunks of 13 (clamped)
        {
            int p0 = pg * 13;
            int p1 = min(p0 + 13, P3D);
            float acc = 0.f;
            for (int p = p0; p < p1; ++p) acc = fmaf(Wv3[j * P3D + p], sX3[p], acc);
            sVp3[pg * 32 + j] = acc;
        }
    }
    __syncthreads();

    // ---------------- Phase 7: head (warp 0 only) -----------------------------
    if (tid < 32) {
        float v2 = 0.f, v3 = 0.f;
        #pragma unroll
        for (int pg = 0; pg < 8; ++pg) {
            v2 += sVp2[pg * 32 + lane];
            v3 += sVp3[pg * 32 + lane];
        }
        sVv[lane]      = v2;
        sVv[32 + lane] = v3;
        __syncwarp();

        float hg = 0.f, z2 = 0.f;
        if (lane < DG) {
            #pragma unroll
            for (int w = 0; w < 8; ++w) hg += sPart[w * DG + lane];
            hg *= (1.f / NPG);
            #pragma unroll
            for (int j = 0; j < 32; ++j) z2 = fmaf(Wo2[lane * 32 + j], sVv[j], z2);
        }
        float y = hg + z2;

        // LayerNorm over 20 dims (lanes >= 20 contribute 0)
        float t = (lane < DG) ? y : 0.f;
        #pragma unroll
        for (int o = 16; o > 0; o >>= 1) t += __shfl_xor_sync(0xffffffffu, t, o);
        float mu = t * (1.f / DG);
        float dv = (lane < DG) ? (y - mu) : 0.f;
        float t2 = dv * dv;
        #pragma unroll
        for (int o = 16; o > 0; o >>= 1) t2 += __shfl_xor_sync(0xffffffffu, t2, o);
        float inv = rsqrtf(t2 * (1.f / DG) + 1e-5f);
        float hg1 = (lane < DG) ? fmaf((y - mu) * inv, g2[lane], be2[lane]) : 0.f;

        float z3 = 0.f;
        if (lane < DG) {
            #pragma unroll
            for (int j = 0; j < 32; ++j) z3 = fmaf(Wo3[lane * 32 + j], sVv[32 + j], z3);
        }
        float y2 = hg1 + z3;
        t = (lane < DG) ? y2 : 0.f;
        #pragma unroll
        for (int o = 16; o > 0; o >>= 1) t += __shfl_xor_sync(0xffffffffu, t, o);
        mu = t * (1.f / DG);
        dv = (lane < DG) ? (y2 - mu) : 0.f;
        t2 = dv * dv;
        #pragma unroll
        for (int o = 16; o > 0; o >>= 1) t2 += __shfl_xor_sync(0xffffffffu, t2, o);
        inv = rsqrtf(t2 * (1.f / DG) + 1e-5f);
        if (lane < DG) sHg2[lane] = fmaf((y2 - mu) * inv, g3[lane], be3[lane]);
        __syncwarp();

        if (lane < 10) {
            float a = bf1[lane];
            #pragma unroll
            for (int d = 0; d < DG; ++d) a = fmaf(Wf1[lane * DG + d], sHg2[d], a);
            sO10[lane] = fmaxf(a, 0.f);
        }
        __syncwarp();

        if (lane == 0) {
            float o = bf2[0];
            #pragma unroll
            for (int i = 0; i < 10; ++i) o = fmaf(Wf2[i], sO10[i], o);
            out[g] = o;
        }
    }
}

extern "C" void kernel_launch(void* const* d_in, const int* in_sizes, int n_in,
                              void* d_out, int out_size) {
    const float* feat     = (const float*)d_in[0];
    const int*   edge_src = (const int*)  d_in[1];
    // d_in[2] = edge_dst (implicit: repeat(arange))
    const float* self_f   = (const float*)d_in[3];
    const float* x3d      = (const float*)d_in[4];
    const float* W1  = (const float*)d_in[5];
    const float* b1  = (const float*)d_in[6];
    const float* W2  = (const float*)d_in[7];
    const float* b2  = (const float*)d_in[8];
    // 9 Wq2, 10 Wk2 unused (softmax over length-1 token == 1)
    const float* Wv2 = (const float*)d_in[11];
    const float* Wo2 = (const float*)d_in[12];
    const float* g2  = (const float*)d_in[13];
    const float* be2 = (const float*)d_in[14];
    // 15 Wq3, 16 Wk3 unused
    const float* Wv3 = (const float*)d_in[17];
    const float* Wo3 = (const float*)d_in[18];
    const float* g3  = (const float*)d_in[19];
    const float* be3 = (const float*)d_in[20];
    const float* Wf1 = (const float*)d_in[21];
    const float* bf1 = (const float*)d_in[22];
    const float* Wf2 = (const float*)d_in[23];
    const float* bf2 = (const float*)d_in[24];
    float* out = (float*)d_out;

    cudaFuncSetAttribute(net_kernel, cudaFuncAttributeMaxDynamicSharedMemorySize,
                         SMEM_BYTES);
    net_kernel<<<512, 256, SMEM_BYTES>>>(feat, edge_src, self_f, x3d,
                                         W1, b1, W2, b2,
                                         Wv2, Wo2, g2, be2,
                                         Wv3, Wo3, g3, be3,
                                         Wf1, bf1, Wf2, bf2, out);
}

// round 7
// speedup vs baseline: 1.1230x; 1.1230x over previous
#include <cuda_runtime.h>
#include <cstdint>

// Fused batched GCN, one CTA per graph (512 x 100 nodes, deg 16), fp32.
// GEMMs use packed fma.rn.f32x2 SIMD over the k-dimension: contiguous LDS.64
// operands, dual-lane accumulators, one horizontal add in the epilogue.
// Layer 2 transform-before-aggregate (aggregation is linear).
// Heads: softmax over a length-1 token == 1 -> Z=(x@Wv^T)@Wo^T; Wq/Wk dead.

#define NPG   100
#define DEG   16
#define DIN   100
#define H1D   100
#define DG    20
#define P2D   200
#define P3D   100

#define PX    100   // feat pitch (floats), float4-aligned rows
#define PA    106   // pitch of A / h1 / W tiles: lane-stride 10 banks -> conflict-free
#define PT    24    // pitch of 20-wide buffers

// ---- shared memory layout (float element offsets) ----
#define OFF_X     0                     // 100*100 = 10000   feat
#define OFF_A     (OFF_X  + 10000)      // 112*106 = 11872   agg1
#define OFF_H     (OFF_A  + 11872)      // 112*106 = 11872   W1 (staged), then h1
#define OFF_W2    (OFF_H  + 11872)      // 32*106  = 3392    W2
#define OFF_T     (OFF_W2 + 3392)       // 100*24  = 2400    t = h1@W2^T
#define OFF_T2    (OFF_T  + 2400)       // 2400              agg2
#define OFF_E     (OFF_T2 + 2400)       // 1600 ints
#define OFF_SF    (OFF_E  + 1600)       // 200
#define OFF_X3    (OFF_SF + 200)        // 100
#define OFF_PART  (OFF_X3 + 100)        // 8*20
#define OFF_VP2   (OFF_PART + 160)      // 256
#define OFF_VP3   (OFF_VP2 + 256)       // 256
#define OFF_VV    (OFF_VP3 + 256)       // 64
#define OFF_HG2   (OFF_VV + 64)         // 20
#define OFF_O10   (OFF_HG2 + 20)        // 12
#define SMEM_ELEMS (OFF_O10 + 16)
#define SMEM_BYTES (SMEM_ELEMS * 4)

typedef unsigned long long u64;

static __device__ __forceinline__ void ffma2(u64& d, u64 a, u64 b) {
    asm("fma.rn.f32x2 %0, %1, %2, %0;" : "+l"(d) : "l"(a), "l"(b));
}
static __device__ __forceinline__ float hsum2(u64 v) {
    float lo = __uint_as_float((unsigned)(v & 0xffffffffu));
    float hi = __uint_as_float((unsigned)(v >> 32));
    return lo + hi;
}

__global__ __launch_bounds__(256, 1)
void net_kernel(const float* __restrict__ feat,
                const int*   __restrict__ edge_src,
                const float* __restrict__ self_feat,
                const float* __restrict__ x3d,
                const float* __restrict__ W1,  const float* __restrict__ b1,
                const float* __restrict__ W2,  const float* __restrict__ b2,
                const float* __restrict__ Wv2, const float* __restrict__ Wo2,
                const float* __restrict__ g2,  const float* __restrict__ be2,
                const float* __restrict__ Wv3, const float* __restrict__ Wo3,
                const float* __restrict__ g3,  const float* __restrict__ be3,
                const float* __restrict__ Wf1, const float* __restrict__ bf1,
                const float* __restrict__ Wf2, const float* __restrict__ bf2,
                float* __restrict__ out)
{
    extern __shared__ float sm[];
    float* sX   = sm + OFF_X;
    float* sA   = sm + OFF_A;
    float* sH   = sm + OFF_H;    // W1 during GEMM1, h1 afterwards
    float* sW2  = sm + OFF_W2;
    float* sT   = sm + OFF_T;
    float* sT2  = sm + OFF_T2;
    int*   sEdge= (int*)(sm + OFF_E);
    float* sSf  = sm + OFF_SF;
    float* sX3  = sm + OFF_X3;
    float* sPart= sm + OFF_PART;
    float* sVp2 = sm + OFF_VP2;
    float* sVp3 = sm + OFF_VP3;
    float* sVv  = sm + OFF_VV;
    float* sHg2 = sm + OFF_HG2;
    float* sO10 = sm + OFF_O10;

    const int g    = blockIdx.x;
    const int tid  = threadIdx.x;
    const int warp = tid >> 5;
    const int lane = tid & 31;

    // ---------------- Phase 1: stage inputs ----------------
    for (int i = tid; i < NPG * DEG; i += 256)
        sEdge[i] = edge_src[g * (NPG * DEG) + i] - g * NPG;
    {
        const float4* fsrc = (const float4*)(feat + (size_t)g * NPG * DIN);
        for (int i4 = tid; i4 < (NPG * DIN) / 4; i4 += 256)
            *(float4*)&sX[i4 * 4] = fsrc[i4];           // pitch 100 == DIN
    }
    // W1 [100 x 100] row-major -> sH pitch 106, copy as float2 pairs
    for (int idx = tid; idx < H1D * (DIN / 2); idx += 256) {
        int o = idx / 50, kp = idx - o * 50;
        *(u64*)&sH[o * PA + 2 * kp] = *(const u64*)&W1[o * DIN + 2 * kp];
    }
    // W2 [20 x 100] -> sW2 pitch 106
    for (int idx = tid; idx < DG * (H1D / 2); idx += 256) {
        int o = idx / 50, kp = idx - o * 50;
        *(u64*)&sW2[o * PA + 2 * kp] = *(const u64*)&W2[o * H1D + 2 * kp];
    }
    for (int i = tid; i < P2D; i += 256) sSf[i] = self_feat[g * P2D + i];
    for (int i = tid; i < P3D; i += 256) sX3[i] = x3d[g * P3D + i];
    __syncthreads();

    // ---------------- Phase 2: aggregation 1 (mean of 16, 100 dims) ----------
    for (int n = warp; n < NPG; n += 8) {
        if (lane < 25) {
            float4 acc = make_float4(0.f, 0.f, 0.f, 0.f);
            int base = n * DEG;
            #pragma unroll
            for (int j = 0; j < DEG; ++j) {
                int s = sEdge[base + j];
                float4 v = *(const float4*)&sX[s * PX + (lane << 2)];
                acc.x += v.x; acc.y += v.y; acc.z += v.z; acc.w += v.w;
            }
            const float inv = 1.f / DEG;
            int c = lane << 2;
            float2 p0 = make_float2(acc.x * inv, acc.y * inv);
            float2 p1 = make_float2(acc.z * inv, acc.w * inv);
            *(float2*)&sA[n * PA + c]     = p0;
            *(float2*)&sA[n * PA + c + 2] = p1;
        }
    }
    __syncthreads();

    // ---------------- Phase 3: GEMM1 (f32x2 over k), 16x16 grid, 7x7 tile ----
    const int ty = tid >> 4, tx = tid & 15;
    {
        u64 acc[7][7];
        #pragma unroll
        for (int i = 0; i < 7; ++i)
            #pragma unroll
            for (int j = 0; j < 7; ++j) acc[i][j] = 0ull;

        #pragma unroll 2
        for (int kp = 0; kp < DIN / 2; ++kp) {
            const int k = kp * 2;
            u64 a2[7], w2[7];
            #pragma unroll
            for (int i = 0; i < 7; ++i)
                a2[i] = *(const u64*)&sA[(ty + 16 * i) * PA + k];
            #pragma unroll
            for (int j = 0; j < 7; ++j)
                w2[j] = *(const u64*)&sH[(tx + 16 * j) * PA + k];
            #pragma unroll
            for (int i = 0; i < 7; ++i)
                #pragma unroll
                for (int j = 0; j < 7; ++j) ffma2(acc[i][j], a2[i], w2[j]);
        }
        __syncthreads();   // all W1 reads done before h1 overwrites sH

        // epilogue: h1 = relu(sum + b1) -> sH
        float bb[7];
        #pragma unroll
        for (int j = 0; j < 7; ++j) {
            int c = tx + 16 * j;
            bb[j] = (c < H1D) ? b1[c] : 0.f;
        }
        #pragma unroll
        for (int i = 0; i < 7; ++i) {
            int r = ty + 16 * i;
            if (r < NPG) {
                #pragma unroll
                for (int j = 0; j < 7; ++j) {
                    int c = tx + 16 * j;
                    if (c < H1D)
                        sH[r * PA + c] = fmaxf(hsum2(acc[i][j]) + bb[j], 0.f);
                }
            }
        }
    }
    __syncthreads();

    // ---------------- Phase 4: GEMM2  t = h1 @ W2^T (pre-bias) ---------------
    {
        u64 acc0[7], acc1[7];
        #pragma unroll
        for (int i = 0; i < 7; ++i) { acc0[i] = 0ull; acc1[i] = 0ull; }

        #pragma unroll 2
        for (int kp = 0; kp < H1D / 2; ++kp) {
            const int k = kp * 2;
            u64 w0 = *(const u64*)&sW2[tx * PA + k];
            u64 w1 = *(const u64*)&sW2[(tx + 16) * PA + k];
            #pragma unroll
            for (int i = 0; i < 7; ++i) {
                u64 a = *(const u64*)&sH[(ty + 16 * i) * PA + k];
                ffma2(acc0[i], a, w0);
                ffma2(acc1[i], a, w1);
            }
        }
        #pragma unroll
        for (int i = 0; i < 7; ++i) {
            int r = ty + 16 * i;
            if (r < NPG) {
                sT[r * PT + tx] = hsum2(acc0[i]);
                if (tx + 16 < DG) sT[r * PT + tx + 16] = hsum2(acc1[i]);
            }
        }
    }
    __syncthreads();

    // ---------------- Phase 5: aggregation 2 (20 dims) -----------------------
    for (int n = warp; n < NPG; n += 8) {
        if (lane < DG) {
            float acc = 0.f;
            int base = n * DEG;
            #pragma unroll
            for (int j = 0; j < DEG; ++j)
                acc += sT[sEdge[base + j] * PT + lane];
            sT2[n * PT + lane] = acc * (1.f / DEG);
        }
    }
    __syncthreads();

    // ---------------- Phase 6: hg partials + attention V partials ------------
    if (lane < DG) {
        float b = b2[lane];
        float acc = 0.f;
        for (int n = warp; n < NPG; n += 8)
            acc += fmaxf(sT2[n * PT + lane] + b, 0.f);
        sPart[warp * DG + lane] = acc;
    }
    {
        int j  = tid & 31;
        int pg = tid >> 5;
        {
            const float* wr = Wv2 + j * P2D + pg * 25;
            const float* sp = sSf + pg * 25;
            float acc = 0.f;
            #pragma unroll
            for (int p = 0; p < 25; ++p) acc = fmaf(wr[p], sp[p], acc);
            sVp2[pg * 32 + j] = acc;
        }
        {
            int p0 = pg * 13, p1 = min(p0 + 13, P3D);
            float acc = 0.f;
            for (int p = p0; p < p1; ++p) acc = fmaf(Wv3[j * P3D + p], sX3[p], acc);
            sVp3[pg * 32 + j] = acc;
        }
    }
    __syncthreads();

    // ---------------- Phase 7: head (warp 0) ---------------------------------
    if (tid < 32) {
        float v2 = 0.f, v3 = 0.f;
        #pragma unroll
        for (int pg = 0; pg < 8; ++pg) {
            v2 += sVp2[pg * 32 + lane];
            v3 += sVp3[pg * 32 + lane];
        }
        sVv[lane]      = v2;
        sVv[32 + lane] = v3;
        __syncwarp();

        float hg = 0.f, z2 = 0.f;
        if (lane < DG) {
            #pragma unroll
            for (int w = 0; w < 8; ++w) hg += sPart[w * DG + lane];
            hg *= (1.f / NPG);
            #pragma unroll
            for (int j = 0; j < 32; ++j) z2 = fmaf(Wo2[lane * 32 + j], sVv[j], z2);
        }
        float y = hg + z2;
        float t = (lane < DG) ? y : 0.f;
        #pragma unroll
        for (int o = 16; o > 0; o >>= 1) t += __shfl_xor_sync(0xffffffffu, t, o);
        float mu = t * (1.f / DG);
        float dv = (lane < DG) ? (y - mu) : 0.f;
        float t2 = dv * dv;
        #pragma unroll
        for (int o = 16; o > 0; o >>= 1) t2 += __shfl_xor_sync(0xffffffffu, t2, o);
        float inv = rsqrtf(t2 * (1.f / DG) + 1e-5f);
        float hg1 = (lane < DG) ? fmaf((y - mu) * inv, g2[lane], be2[lane]) : 0.f;

        float z3 = 0.f;
        if (lane < DG) {
            #pragma unroll
            for (int j = 0; j < 32; ++j) z3 = fmaf(Wo3[lane * 32 + j], sVv[32 + j], z3);
        }
        float y2 = hg1 + z3;
        t = (lane < DG) ? y2 : 0.f;
        #pragma unroll
        for (int o = 16; o > 0; o >>= 1) t += __shfl_xor_sync(0xffffffffu, t, o);
        mu = t * (1.f / DG);
        dv = (lane < DG) ? (y2 - mu) : 0.f;
        t2 = dv * dv;
        #pragma unroll
        for (int o = 16; o > 0; o >>= 1) t2 += __shfl_xor_sync(0xffffffffu, t2, o);
        inv = rsqrtf(t2 * (1.f / DG) + 1e-5f);
        if (lane < DG) sHg2[lane] = fmaf((y2 - mu) * inv, g3[lane], be3[lane]);
        __syncwarp();

        if (lane < 10) {
            float a = bf1[lane];
            #pragma unroll
            for (int d = 0; d < DG; ++d) a = fmaf(Wf1[lane * DG + d], sHg2[d], a);
            sO10[lane] = fmaxf(a, 0.f);
        }
        __syncwarp();

        if (lane == 0) {
            float o = bf2[0];
            #pragma unroll
            for (int i = 0; i < 10; ++i) o = fmaf(Wf2[i], sO10[i], o);
            out[g] = o;
        }
    }
}

extern "C" void kernel_launch(void* const* d_in, const int* in_sizes, int n_in,
                              void* d_out, int out_size) {
    const float* feat     = (const float*)d_in[0];
    const int*   edge_src = (const int*)  d_in[1];
    // d_in[2] = edge_dst (implicit: repeat(arange))
    const float* self_f   = (const float*)d_in[3];
    const float* x3d      = (const float*)d_in[4];
    const float* W1  = (const float*)d_in[5];
    const float* b1  = (const float*)d_in[6];
    const float* W2  = (const float*)d_in[7];
    const float* b2  = (const float*)d_in[8];
    // 9 Wq2, 10 Wk2 unused (softmax over length-1 token == 1)
    const float* Wv2 = (const float*)d_in[11];
    const float* Wo2 = (const float*)d_in[12];
    const float* g2  = (const float*)d_in[13];
    const float* be2 = (const float*)d_in[14];
    // 15 Wq3, 16 Wk3 unused
    const float* Wv3 = (const float*)d_in[17];
    const float* Wo3 = (const float*)d_in[18];
    const float* g3  = (const float*)d_in[19];
    const float* be3 = (const float*)d_in[20];
    const float* Wf1 = (const float*)d_in[21];
    const float* bf1 = (const float*)d_in[22];
    const float* Wf2 = (const float*)d_in[23];
    const float* bf2 = (const float*)d_in[24];
    float* out = (float*)d_out;

    cudaFuncSetAttribute(net_kernel, cudaFuncAttributeMaxDynamicSharedMemorySize,
                         SMEM_BYTES);
    net_kernel<<<512, 256, SMEM_BYTES>>>(feat, edge_src, self_f, x3d,
                                         W1, b1, W2, b2,
                                         Wv2, Wo2, g2, be2,
                                         Wv3, Wo3, g3, be3,
                                         Wf1, bf1, Wf2, bf2, out);
}

// round 9
// speedup vs baseline: 1.1441x; 1.0187x over previous
#include <cuda_runtime.h>
#include <cstdint>

// Fused batched GCN, one CTA per graph (512 x 100 nodes, deg 16), fp32.
// 512 threads / 16 warps (4 per SMSP) for latency coverage.
// GEMMs use packed fma.rn.f32x2 over k: contiguous LDS.64 operands,
// dual-lane accumulators, horizontal add in epilogue.
// Layer 2 transform-before-aggregate. Heads: softmax over length-1 token == 1
// -> Z=(x@Wv^T)@Wo^T; Wq/Wk dead.

#define NPG   100
#define DEG   16
#define DIN   100
#define H1D   100
#define DG    20
#define P2D   200
#define P3D   100

#define PX    100   // feat pitch (floats)
#define PA    106   // pitch of A / h1 / W tiles (conflict-free LDS.64 phases)
#define PT    21    // pitch of 20-wide buffers (odd -> conflict-free scalar)

// ---- shared memory layout (float element offsets) ----
#define OFF_X     0                     // 10000  feat
#define OFF_A     (OFF_X  + 10000)      // 112*106 = 11872  agg1
#define OFF_H     (OFF_A  + 11872)      // 112*106 = 11872  W1 staged, then h1
#define OFF_W2    (OFF_H  + 11872)      // 20*106  = 2120   W2
#define OFF_T     (OFF_W2 + 2120)       // 100*21  = 2100   t = h1@W2^T
#define OFF_T2    (OFF_T  + 2100)       // 2100             agg2
#define OFF_E     (OFF_T2 + 2100)       // 1600 ints
#define OFF_SF    (OFF_E  + 1600)       // 200
#define OFF_X3    (OFF_SF + 200)        // 100
#define OFF_PART  (OFF_X3 + 100)        // 16*20
#define OFF_VP2   (OFF_PART + 320)      // 512
#define OFF_VP3   (OFF_VP2 + 512)       // 512
#define OFF_VV    (OFF_VP3 + 512)       // 64
#define OFF_HG2   (OFF_VV + 64)         // 20
#define OFF_O10   (OFF_HG2 + 20)        // 12
#define SMEM_ELEMS (OFF_O10 + 16)
#define SMEM_BYTES (SMEM_ELEMS * 4)

typedef unsigned long long u64;

static __device__ __forceinline__ void ffma2(u64& d, u64 a, u64 b) {
    asm("fma.rn.f32x2 %0, %1, %2, %0;" : "+l"(d) : "l"(a), "l"(b));
}
static __device__ __forceinline__ float hsum2(u64 v) {
    float lo = __uint_as_float((unsigned)(v & 0xffffffffu));
    float hi = __uint_as_float((unsigned)(v >> 32));
    return lo + hi;
}

__global__ __launch_bounds__(512, 1)
void net_kernel(const float* __restrict__ feat,
                const int*   __restrict__ edge_src,
                const float* __restrict__ self_feat,
                const float* __restrict__ x3d,
                const float* __restrict__ W1,  const float* __restrict__ b1,
                const float* __restrict__ W2,  const float* __restrict__ b2,
                const float* __restrict__ Wv2, const float* __restrict__ Wo2,
                const float* __restrict__ g2,  const float* __restrict__ be2,
                const float* __restrict__ Wv3, const float* __restrict__ Wo3,
                const float* __restrict__ g3,  const float* __restrict__ be3,
                const float* __restrict__ Wf1, const float* __restrict__ bf1,
                const float* __restrict__ Wf2, const float* __restrict__ bf2,
                float* __restrict__ out)
{
    extern __shared__ float sm[];
    float* sX   = sm + OFF_X;
    float* sA   = sm + OFF_A;
    float* sH   = sm + OFF_H;    // W1 during GEMM1, h1 afterwards
    float* sW2  = sm + OFF_W2;
    float* sT   = sm + OFF_T;
    float* sT2  = sm + OFF_T2;
    int*   sEdge= (int*)(sm + OFF_E);
    float* sSf  = sm + OFF_SF;
    float* sX3  = sm + OFF_X3;
    float* sPart= sm + OFF_PART;
    float* sVp2 = sm + OFF_VP2;
    float* sVp3 = sm + OFF_VP3;
    float* sVv  = sm + OFF_VV;
    float* sHg2 = sm + OFF_HG2;
    float* sO10 = sm + OFF_O10;

    const int g    = blockIdx.x;
    const int tid  = threadIdx.x;
    const int warp = tid >> 5;
    const int lane = tid & 31;

    // ---------------- Phase 1: stage inputs ----------------
    for (int i = tid; i < NPG * DEG; i += 512)
        sEdge[i] = edge_src[g * (NPG * DEG) + i] - g * NPG;
    {
        const float4* fsrc = (const float4*)(feat + (size_t)g * NPG * DIN);
        for (int i4 = tid; i4 < (NPG * DIN) / 4; i4 += 512)
            *(float4*)&sX[i4 * 4] = fsrc[i4];           // pitch 100 == DIN
    }
    // W1 [100 x 100] -> sH pitch 106 (u64 pairs)
    for (int idx = tid; idx < H1D * (DIN / 2); idx += 512) {
        int o = idx / 50, kp = idx - o * 50;
        *(u64*)&sH[o * PA + 2 * kp] = *(const u64*)&W1[o * DIN + 2 * kp];
    }
    // W2 [20 x 100] -> sW2 pitch 106
    for (int idx = tid; idx < DG * (H1D / 2); idx += 512) {
        int o = idx / 50, kp = idx - o * 50;
        *(u64*)&sW2[o * PA + 2 * kp] = *(const u64*)&W2[o * H1D + 2 * kp];
    }
    for (int i = tid; i < P2D; i += 512) sSf[i] = self_feat[g * P2D + i];
    for (int i = tid; i < P3D; i += 512) sX3[i] = x3d[g * P3D + i];
    __syncthreads();

    // ---------------- Phase 2: aggregation 1 (mean of 16, 100 dims) ----------
    for (int n = warp; n < NPG; n += 16) {
        if (lane < 25) {
            float4 acc = make_float4(0.f, 0.f, 0.f, 0.f);
            int base = n * DEG;
            #pragma unroll
            for (int j = 0; j < DEG; ++j) {
                int s = sEdge[base + j];
                float4 v = *(const float4*)&sX[s * PX + (lane << 2)];
                acc.x += v.x; acc.y += v.y; acc.z += v.z; acc.w += v.w;
            }
            const float inv = 1.f / DEG;
            int c = lane << 2;
            *(float2*)&sA[n * PA + c]     = make_float2(acc.x * inv, acc.y * inv);
            *(float2*)&sA[n * PA + c + 2] = make_float2(acc.z * inv, acc.w * inv);
        }
    }
    __syncthreads();

    // ---------------- Phase 3: GEMM1 (f32x2 over k), 32x16 grid, 7x4 tile ----
    {
        const int ty = warp;            // rows ty + 16*i, i<7
        const int tx = lane;            // cols tx + 32*j, j<4
        int wrow[4];
        #pragma unroll
        for (int j = 0; j < 4; ++j) {
            int c = tx + 32 * j;
            wrow[j] = (c < H1D) ? c : 0;
        }

        u64 acc[7][4];
        #pragma unroll
        for (int i = 0; i < 7; ++i)
            #pragma unroll
            for (int j = 0; j < 4; ++j) acc[i][j] = 0ull;

        #pragma unroll 2
        for (int kp = 0; kp < DIN / 2; ++kp) {
            const int k = kp * 2;
            u64 a2[7], w2[4];
            #pragma unroll
            for (int i = 0; i < 7; ++i)           // broadcast (warp-uniform addr)
                a2[i] = *(const u64*)&sA[(ty + 16 * i) * PA + k];
            #pragma unroll
            for (int j = 0; j < 4; ++j)
                w2[j] = *(const u64*)&sH[wrow[j] * PA + k];
            #pragma unroll
            for (int i = 0; i < 7; ++i)
                #pragma unroll
                for (int j = 0; j < 4; ++j) ffma2(acc[i][j], a2[i], w2[j]);
        }
        __syncthreads();   // all W1 reads done before h1 overwrites sH

        float bb[4];
        #pragma unroll
        for (int j = 0; j < 4; ++j) {
            int c = tx + 32 * j;
            bb[j] = (c < H1D) ? b1[c] : 0.f;
        }
        #pragma unroll
        for (int i = 0; i < 7; ++i) {
            int r = ty + 16 * i;
            if (r < NPG) {
                #pragma unroll
                for (int j = 0; j < 4; ++j) {
                    int c = tx + 32 * j;
                    if (c < H1D)
                        sH[r * PA + c] = fmaxf(hsum2(acc[i][j]) + bb[j], 0.f);
                }
            }
        }
    }
    __syncthreads();

    // ---------------- Phase 4: GEMM2  t = h1 @ W2^T (pre-bias) ---------------
    {
        const int wrow = (lane < DG) ? lane : 0;  // col = lane
        u64 acc[7];
        #pragma unroll
        for (int i = 0; i < 7; ++i) acc[i] = 0ull;

        #pragma unroll 2
        for (int kp = 0; kp < H1D / 2; ++kp) {
            const int k = kp * 2;
            u64 w = *(const u64*)&sW2[wrow * PA + k];
            #pragma unroll
            for (int i = 0; i < 7; ++i) {         // broadcast row loads
                u64 a = *(const u64*)&sH[(warp + 16 * i) * PA + k];
                ffma2(acc[i], a, w);
            }
        }
        if (lane < DG) {
            #pragma unroll
            for (int i = 0; i < 7; ++i) {
                int r = warp + 16 * i;
                if (r < NPG) sT[r * PT + lane] = hsum2(acc[i]);
            }
        }
    }
    __syncthreads();

    // ---------------- Phase 5: aggregation 2 (20 dims) -----------------------
    for (int n = warp; n < NPG; n += 16) {
        if (lane < DG) {
            float acc = 0.f;
            int base = n * DEG;
            #pragma unroll
            for (int j = 0; j < DEG; ++j)
                acc += sT[sEdge[base + j] * PT + lane];
            sT2[n * PT + lane] = acc * (1.f / DEG);
        }
    }
    __syncthreads();

    // ---------------- Phase 6: hg partials + attention V partials ------------
    if (lane < DG) {
        float b = b2[lane];
        float acc = 0.f;
        for (int n = warp; n < NPG; n += 16)
            acc += fmaxf(sT2[n * PT + lane] + b, 0.f);
        sPart[warp * DG + lane] = acc;
    }
    {
        int j  = lane;
        int pg = warp;                  // 16 chunks
        {   // v2: 200 dims in 16 chunks of 13 (clamped)
            int p0 = pg * 13, p1 = min(p0 + 13, P2D);
            float acc = 0.f;
            for (int p = p0; p < p1; ++p) acc = fmaf(Wv2[j * P2D + p], sSf[p], acc);
            sVp2[pg * 32 + j] = acc;
        }
        {   // v3: 100 dims in 16 chunks of 7 (clamped)
            int p0 = pg * 7, p1 = min(p0 + 7, P3D);
            float acc = 0.f;
            for (int p = p0; p < p1; ++p) acc = fmaf(Wv3[j * P3D + p], sX3[p], acc);
            sVp3[pg * 32 + j] = acc;
        }
    }
    __syncthreads();

    // ---------------- Phase 7: head (warp 0) ---------------------------------
    if (tid < 32) {
        float v2 = 0.f, v3 = 0.f;
        #pragma unroll
        for (int pg = 0; pg < 16; ++pg) {
            v2 += sVp2[pg * 32 + lane];
            v3 += sVp3[pg * 32 + lane];
        }
        sVv[lane]      = v2;
        sVv[32 + lane] = v3;
        __syncwarp();

        float hg = 0.f, z2 = 0.f;
        if (lane < DG) {
            #pragma unroll
            for (int w = 0; w < 16; ++w) hg += sPart[w * DG + lane];
            hg *= (1.f / NPG);
            #pragma unroll
            for (int j = 0; j < 32; ++j) z2 = fmaf(Wo2[lane * 32 + j], sVv[j], z2);
        }
        float y = hg + z2;
        float t = (lane < DG) ? y : 0.f;
        #pragma unroll
        for (int o = 16; o > 0; o >>= 1) t += __shfl_xor_sync(0xffffffffu, t, o);
        float mu = t * (1.f / DG);
        float dv = (lane < DG) ? (y - mu) : 0.f;
        float t2 = dv * dv;
        #pragma unroll
        for (int o = 16; o > 0; o >>= 1) t2 += __shfl_xor_sync(0xffffffffu, t2, o);
        float inv = rsqrtf(t2 * (1.f / DG) + 1e-5f);
        float hg1 = (lane < DG) ? fmaf((y - mu) * inv, g2[lane], be2[lane]) : 0.f;

        float z3 = 0.f;
        if (lane < DG) {
            #pragma unroll
            for (int j = 0; j < 32; ++j) z3 = fmaf(Wo3[lane * 32 + j], sVv[32 + j], z3);
        }
        float y2 = hg1 + z3;
        t = (lane < DG) ? y2 : 0.f;
        #pragma unroll
        for (int o = 16; o > 0; o >>= 1) t += __shfl_xor_sync(0xffffffffu, t, o);
        mu = t * (1.f / DG);
        dv = (lane < DG) ? (y2 - mu) : 0.f;
        t2 = dv * dv;
        #pragma unroll
        for (int o = 16; o > 0; o >>= 1) t2 += __shfl_xor_sync(0xffffffffu, t2, o);
        inv = rsqrtf(t2 * (1.f / DG) + 1e-5f);
        if (lane < DG) sHg2[lane] = fmaf((y2 - mu) * inv, g3[lane], be3[lane]);
        __syncwarp();

        if (lane < 10) {
            float a = bf1[lane];
            #pragma unroll
            for (int d = 0; d < DG; ++d) a = fmaf(Wf1[lane * DG + d], sHg2[d], a);
            sO10[lane] = fmaxf(a, 0.f);
        }
        __syncwarp();

        if (lane == 0) {
            float o = bf2[0];
            #pragma unroll
            for (int i = 0; i < 10; ++i) o = fmaf(Wf2[i], sO10[i], o);
            out[g] = o;
        }
    }
}

extern "C" void kernel_launch(void* const* d_in, const int* in_sizes, int n_in,
                              void* d_out, int out_size) {
    const float* feat     = (const float*)d_in[0];
    const int*   edge_src = (const int*)  d_in[1];
    // d_in[2] = edge_dst (implicit: repeat(arange))
    const float* self_f   = (const float*)d_in[3];
    const float* x3d      = (const float*)d_in[4];
    const float* W1  = (const float*)d_in[5];
    const float* b1  = (const float*)d_in[6];
    const float* W2  = (const float*)d_in[7];
    const float* b2  = (const float*)d_in[8];
    // 9 Wq2, 10 Wk2 unused (softmax over length-1 token == 1)
    const float* Wv2 = (const float*)d_in[11];
    const float* Wo2 = (const float*)d_in[12];
    const float* g2  = (const float*)d_in[13];
    const float* be2 = (const float*)d_in[14];
    // 15 Wq3, 16 Wk3 unused
    const float* Wv3 = (const float*)d_in[17];
    const float* Wo3 = (const float*)d_in[18];
    const float* g3  = (const float*)d_in[19];
    const float* be3 = (const float*)d_in[20];
    const float* Wf1 = (const float*)d_in[21];
    const float* bf1 = (const float*)d_in[22];
    const float* Wf2 = (const float*)d_in[23];
    const float* bf2 = (const float*)d_in[24];
    float* out = (float*)d_out;

    cudaFuncSetAttribute(net_kernel, cudaFuncAttributeMaxDynamicSharedMemorySize,
                         SMEM_BYTES);
    net_kernel<<<512, 512, SMEM_BYTES>>>(feat, edge_src, self_f, x3d,
                                         W1, b1, W2, b2,
                                         Wv2, Wo2, g2, be2,
                                         Wv3, Wo3, g3, be3,
                                         Wf1, bf1, Wf2, bf2, out);
}